// round 5
// baseline (speedup 1.0000x reference)
#include <cuda_runtime.h>

#define L_MAX   2048
#define BATCH   64
#define DDIM    256
#define CCH     512
#define NCHUNK  16
#define ROWS_PER_CHUNK (L_MAX / NCHUNK)   // 128
#define ROWS_PER_WARP  (ROWS_PER_CHUNK / 8) // 16

#define HQ_BLOCKS 2048
#define M_BLOCKS  96

// ---- scratch (no allocations allowed) ----
__device__ float g_hq[BATCH * DDIM];
__device__ float g_M[3 * DDIM];
__device__ float g_hardU[L_MAX * BATCH];
__device__ float g_part[BATCH * NCHUNK * DDIM];
__device__ float g_denp[BATCH * NCHUNK];

__device__ __forceinline__ float ftanh(float x) {
    float e = __expf(2.0f * x);
    return 1.0f - __fdividef(2.0f, e + 1.0f);
}

// ---------------------------------------------------------------------------
// Kernel 1: prep (warp-per-output, fully coalesced). Unchanged (7.2 us).
// ---------------------------------------------------------------------------
__global__ __launch_bounds__(256) void prep_kernel(
    const float* __restrict__ ht, const float* __restrict__ Wq,
    const float* __restrict__ Wap, const float* __restrict__ Wc,
    const float* __restrict__ bap)
{
    int warp = threadIdx.x >> 5, lane = threadIdx.x & 31;

    if (blockIdx.x < HQ_BLOCKS) {
        int gw = blockIdx.x * 8 + warp;
        int b = gw >> 8;
        int d = gw & 255;
        const float* htr = ht + b * DDIM;
        const float* wqr = Wq + (size_t)d * DDIM;
        float a = 0.f;
#pragma unroll
        for (int i = 0; i < DDIM / 32; i++) {
            int e = lane + 32 * i;
            a += htr[e] * wqr[e];
        }
#pragma unroll
        for (int off = 16; off; off >>= 1)
            a += __shfl_xor_sync(0xffffffffu, a, off);
        if (lane == 0) g_hq[b * DDIM + d] = a + bap[d];
    } else {
        int gw = (blockIdx.x - HQ_BLOCKS) * 8 + warp;
        int dd = gw / 3;
        int k  = gw % 3;
        const float* wr = Wap + (size_t)dd * CCH;
        float m = 0.f;
#pragma unroll
        for (int i = 0; i < CCH / 32; i++) {
            int c = lane + 32 * i;
            m += wr[c] * Wc[c * 3 + k];
        }
#pragma unroll
        for (int off = 16; off; off >>= 1)
            m += __shfl_xor_sync(0xffffffffu, m, off);
        if (lane == 0) g_M[k * DDIM + dd] = m;
    }
}

// ---------------------------------------------------------------------------
// Kernel 2: main, fused streaming loop (R3 structure), 2-row batches,
// UNCONDITIONAL val prefetch: key+val loads for both rows issue together
// (no dependent load chain), accumulate acc += h*v (h==0 -> no-op).
// ---------------------------------------------------------------------------
__global__ __launch_bounds__(256) void main_kernel(
    const float* __restrict__ ctx_val, const float* __restrict__ ctx_key,
    const float* __restrict__ ctx_mask, const float* __restrict__ past,
    const float* __restrict__ W_attn, const float* __restrict__ b_attn)
{
    __shared__ float s_acc[8 * DDIM];
    __shared__ float s_cnt[8];

    int b = blockIdx.y, chunk = blockIdx.x;
    int w = threadIdx.x >> 5, lane = threadIdx.x & 31;
    int d0 = lane * 4;        // [0,128)
    int d1 = 128 + lane * 4;  // [128,256)

    float4 hq0 = *reinterpret_cast<const float4*>(&g_hq[b * DDIM + d0]);
    float4 hq1 = *reinterpret_cast<const float4*>(&g_hq[b * DDIM + d1]);
    float4 M00 = *reinterpret_cast<const float4*>(&g_M[d0]);
    float4 M01 = *reinterpret_cast<const float4*>(&g_M[d1]);
    float4 M10 = *reinterpret_cast<const float4*>(&g_M[DDIM + d0]);
    float4 M11 = *reinterpret_cast<const float4*>(&g_M[DDIM + d1]);
    float4 M20 = *reinterpret_cast<const float4*>(&g_M[2 * DDIM + d0]);
    float4 M21 = *reinterpret_cast<const float4*>(&g_M[2 * DDIM + d1]);
    float4 Wa0 = *reinterpret_cast<const float4*>(&W_attn[d0]);
    float4 Wa1 = *reinterpret_cast<const float4*>(&W_attn[d1]);
    float ba = b_attn[0];

    float4 acc0 = make_float4(0.f, 0.f, 0.f, 0.f);
    float4 acc1 = make_float4(0.f, 0.f, 0.f, 0.f);
    float hsum = 0.f;

    int lbase = chunk * ROWS_PER_CHUNK + w * ROWS_PER_WARP;
#pragma unroll 2
    for (int rb = 0; rb < ROWS_PER_WARP / 2; rb++) {
        int l0 = lbase + rb * 2;
        float4 ka[2], kb[2], va[2], vb[2];
        // issue all 8 independent LDG.128 up front — no dependent chain
#pragma unroll
        for (int j = 0; j < 2; j++) {
            size_t row = ((size_t)(l0 + j) * BATCH + b) * DDIM;
            ka[j] = *reinterpret_cast<const float4*>(ctx_key + row + d0);
            kb[j] = *reinterpret_cast<const float4*>(ctx_key + row + d1);
            va[j] = *reinterpret_cast<const float4*>(ctx_val + row + d0);
            vb[j] = *reinterpret_cast<const float4*>(ctx_val + row + d1);
        }

        float sc[2];
#pragma unroll
        for (int j = 0; j < 2; j++) {
            int l = l0 + j;
            float pm = (l > 0)         ? past[b * L_MAX + l - 1] : 0.f;
            float p0 =                   past[b * L_MAX + l];
            float pp = (l < L_MAX - 1) ? past[b * L_MAX + l + 1] : 0.f;
            float s;
            s  = Wa0.x * ftanh(ka[j].x + hq0.x + pm * M00.x + p0 * M10.x + pp * M20.x);
            s += Wa0.y * ftanh(ka[j].y + hq0.y + pm * M00.y + p0 * M10.y + pp * M20.y);
            s += Wa0.z * ftanh(ka[j].z + hq0.z + pm * M00.z + p0 * M10.z + pp * M20.z);
            s += Wa0.w * ftanh(ka[j].w + hq0.w + pm * M00.w + p0 * M10.w + pp * M20.w);
            s += Wa1.x * ftanh(kb[j].x + hq1.x + pm * M01.x + p0 * M11.x + pp * M21.x);
            s += Wa1.y * ftanh(kb[j].y + hq1.y + pm * M01.y + p0 * M11.y + pp * M21.y);
            s += Wa1.z * ftanh(kb[j].z + hq1.z + pm * M01.z + p0 * M11.z + pp * M21.z);
            s += Wa1.w * ftanh(kb[j].w + hq1.w + pm * M01.w + p0 * M11.w + pp * M21.w);
            sc[j] = s;
        }
        // interleaved reductions for the two rows
#pragma unroll
        for (int off = 16; off; off >>= 1) {
            sc[0] += __shfl_xor_sync(0xffffffffu, sc[0], off);
            sc[1] += __shfl_xor_sync(0xffffffffu, sc[1], off);
        }

#pragma unroll
        for (int j = 0; j < 2; j++) {
            int l = l0 + j;
            float h = (sc[j] + ba >= 0.f) ? ctx_mask[l * BATCH + b] : 0.f;
            if (lane == 0) g_hardU[l * BATCH + b] = h;
            hsum += h;
            // h==0 rows contribute nothing; FMA always (data already in regs)
            acc0.x += h * va[j].x; acc0.y += h * va[j].y;
            acc0.z += h * va[j].z; acc0.w += h * va[j].w;
            acc1.x += h * vb[j].x; acc1.y += h * vb[j].y;
            acc1.z += h * vb[j].z; acc1.w += h * vb[j].w;
        }
    }

    *reinterpret_cast<float4*>(&s_acc[w * DDIM + d0]) = acc0;
    *reinterpret_cast<float4*>(&s_acc[w * DDIM + d1]) = acc1;
    if (lane == 0) s_cnt[w] = hsum;
    __syncthreads();

    int d = threadIdx.x;
    float p = 0.f;
#pragma unroll
    for (int ww = 0; ww < 8; ww++) p += s_acc[ww * DDIM + d];
    g_part[((size_t)b * NCHUNK + chunk) * DDIM + d] = p;

    if (threadIdx.x == 0) {
        float c = 0.f;
#pragma unroll
        for (int ww = 0; ww < 8; ww++) c += s_cnt[ww];
        g_denp[b * NCHUNK + chunk] = c;
    }
}

// ---------------------------------------------------------------------------
// Kernel 3: finish. Normalize; out = concat(ct.flat, hard.flat)
// ---------------------------------------------------------------------------
__global__ __launch_bounds__(256) void finish_kernel(float* __restrict__ out)
{
    int i = blockIdx.x * blockDim.x + threadIdx.x;
    if (i < BATCH * DDIM) {
        int b = i >> 8;
        int d = i & (DDIM - 1);
        float den = 0.f;
#pragma unroll
        for (int c = 0; c < NCHUNK; c++) den += g_denp[b * NCHUNK + c];
        float ct = 0.f;
#pragma unroll
        for (int c = 0; c < NCHUNK; c++)
            ct += g_part[((size_t)b * NCHUNK + c) * DDIM + d];
        out[i] = ct / (den + 1e-10f);
    } else if (i < BATCH * DDIM + L_MAX * BATCH) {
        int j = i - BATCH * DDIM;
        int b = j & (BATCH - 1);
        float den = 0.f;
#pragma unroll
        for (int c = 0; c < NCHUNK; c++) den += g_denp[b * NCHUNK + c];
        out[i] = g_hardU[j] / (den + 1e-10f);
    }
}

// ---------------------------------------------------------------------------
extern "C" void kernel_launch(void* const* d_in, const int* in_sizes, int n_in,
                              void* d_out, int out_size)
{
    (void)in_sizes; (void)n_in; (void)out_size;
    const float* ctx_val  = (const float*)d_in[0];
    const float* ctx_key  = (const float*)d_in[1];
    const float* ctx_mask = (const float*)d_in[2];
    const float* past     = (const float*)d_in[3];
    const float* ht       = (const float*)d_in[4];
    const float* Wc       = (const float*)d_in[5];
    const float* Wq       = (const float*)d_in[6];
    const float* Wap      = (const float*)d_in[7];
    const float* bap      = (const float*)d_in[8];
    const float* Wattn    = (const float*)d_in[9];
    const float* battn    = (const float*)d_in[10];
    float* out = (float*)d_out;

    prep_kernel<<<HQ_BLOCKS + M_BLOCKS, 256>>>(ht, Wq, Wap, Wc, bap);

    dim3 grid(NCHUNK, BATCH);
    main_kernel<<<grid, 256>>>(ctx_val, ctx_key, ctx_mask, past, Wattn, battn);

    int total = BATCH * DDIM + L_MAX * BATCH;
    finish_kernel<<<(total + 255) / 256, 256>>>(out);
}

// round 7
// speedup vs baseline: 1.2962x; 1.2962x over previous
#include <cuda_runtime.h>

#define L_MAX   2048
#define BATCH   64
#define DDIM    256
#define CCH     512
#define NCHUNK  16
#define ROWS_PER_CHUNK (L_MAX / NCHUNK)   // 128
#define ROWS_PER_WARP  (ROWS_PER_CHUNK / 8) // 16

#define HQ_BLOCKS 2048
#define M_BLOCKS  96

// ---- scratch (no allocations allowed) ----
__device__ float g_hq[BATCH * DDIM];
__device__ float g_M[3 * DDIM];
__device__ float g_hardU[L_MAX * BATCH];
__device__ float g_part[BATCH * NCHUNK * DDIM];
__device__ float g_denp[BATCH * NCHUNK];

__device__ __forceinline__ float ftanh(float x) {
    float e = __expf(2.0f * x);
    return 1.0f - __fdividef(2.0f, e + 1.0f);
}

// ---------------------------------------------------------------------------
// Kernel 1: prep (warp-per-output, fully coalesced). Unchanged (7.2 us).
// ---------------------------------------------------------------------------
__global__ __launch_bounds__(256) void prep_kernel(
    const float* __restrict__ ht, const float* __restrict__ Wq,
    const float* __restrict__ Wap, const float* __restrict__ Wc,
    const float* __restrict__ bap)
{
    int warp = threadIdx.x >> 5, lane = threadIdx.x & 31;

    if (blockIdx.x < HQ_BLOCKS) {
        int gw = blockIdx.x * 8 + warp;
        int b = gw >> 8;
        int d = gw & 255;
        const float* htr = ht + b * DDIM;
        const float* wqr = Wq + (size_t)d * DDIM;
        float a = 0.f;
#pragma unroll
        for (int i = 0; i < DDIM / 32; i++) {
            int e = lane + 32 * i;
            a += htr[e] * wqr[e];
        }
#pragma unroll
        for (int off = 16; off; off >>= 1)
            a += __shfl_xor_sync(0xffffffffu, a, off);
        if (lane == 0) g_hq[b * DDIM + d] = a + bap[d];
    } else {
        int gw = (blockIdx.x - HQ_BLOCKS) * 8 + warp;
        int dd = gw / 3;
        int k  = gw % 3;
        const float* wr = Wap + (size_t)dd * CCH;
        float m = 0.f;
#pragma unroll
        for (int i = 0; i < CCH / 32; i++) {
            int c = lane + 32 * i;
            m += wr[c] * Wc[c * 3 + k];
        }
#pragma unroll
        for (int off = 16; off; off >>= 1)
            m += __shfl_xor_sync(0xffffffffu, m, off);
        if (lane == 0) g_M[k * DDIM + dd] = m;
    }
}

// ---------------------------------------------------------------------------
// Kernel 2: main — R3 structure (conditional val load); M + past halo in
// shared memory; regs capped for 4 blocks/SM occupancy.
// All float4-accessed shared arrays are 16B-aligned (R6 crash fix).
// ---------------------------------------------------------------------------
__global__ __launch_bounds__(256, 4) void main_kernel(
    const float* __restrict__ ctx_val, const float* __restrict__ ctx_key,
    const float* __restrict__ ctx_mask, const float* __restrict__ past,
    const float* __restrict__ W_attn, const float* __restrict__ b_attn)
{
    __shared__ alignas(16) float s_M[3 * DDIM];     // fused conv weights
    __shared__ alignas(16) float s_acc[8 * DDIM];   // warp partials
    __shared__ alignas(16) float s_past[ROWS_PER_CHUNK + 4]; // halo, padded
    __shared__ float s_cnt[8];

    int b = blockIdx.y, chunk = blockIdx.x;
    int w = threadIdx.x >> 5, lane = threadIdx.x & 31;
    int d0 = lane * 4;        // [0,128)
    int d1 = 128 + lane * 4;  // [128,256)

    // stage block-shared constants
    if (threadIdx.x < 3 * DDIM / 4) {
        reinterpret_cast<float4*>(s_M)[threadIdx.x] =
            reinterpret_cast<const float4*>(g_M)[threadIdx.x];
    }
    {
        int i = threadIdx.x;
        if (i < ROWS_PER_CHUNK + 2) {
            int g = chunk * ROWS_PER_CHUNK + i - 1;  // l-1 .. l+128
            s_past[i] = (g >= 0 && g < L_MAX) ? past[b * L_MAX + g] : 0.f;
        }
    }
    __syncthreads();

    float4 hq0 = *reinterpret_cast<const float4*>(&g_hq[b * DDIM + d0]);
    float4 hq1 = *reinterpret_cast<const float4*>(&g_hq[b * DDIM + d1]);
    float4 Wa0 = *reinterpret_cast<const float4*>(&W_attn[d0]);
    float4 Wa1 = *reinterpret_cast<const float4*>(&W_attn[d1]);
    float ba = b_attn[0];

    float4 acc0 = make_float4(0.f, 0.f, 0.f, 0.f);
    float4 acc1 = make_float4(0.f, 0.f, 0.f, 0.f);
    float hsum = 0.f;

    int lbase = chunk * ROWS_PER_CHUNK + w * ROWS_PER_WARP;
    for (int r = 0; r < ROWS_PER_WARP; r++) {
        int l = lbase + r;
        int lr = w * ROWS_PER_WARP + r;            // local row in chunk
        size_t row = ((size_t)l * BATCH + b) * DDIM;
        float4 k0 = *reinterpret_cast<const float4*>(ctx_key + row + d0);
        float4 k1 = *reinterpret_cast<const float4*>(ctx_key + row + d1);

        float pm = s_past[lr];
        float p0 = s_past[lr + 1];
        float pp = s_past[lr + 2];

        // M from smem (LDS.128, conflict-free broadcast-free stride)
        float4 m00 = *reinterpret_cast<const float4*>(&s_M[d0]);
        float4 m01 = *reinterpret_cast<const float4*>(&s_M[d1]);
        float4 m10 = *reinterpret_cast<const float4*>(&s_M[DDIM + d0]);
        float4 m11 = *reinterpret_cast<const float4*>(&s_M[DDIM + d1]);
        float4 m20 = *reinterpret_cast<const float4*>(&s_M[2 * DDIM + d0]);
        float4 m21 = *reinterpret_cast<const float4*>(&s_M[2 * DDIM + d1]);

        float s;
        s  = Wa0.x * ftanh(k0.x + hq0.x + pm * m00.x + p0 * m10.x + pp * m20.x);
        s += Wa0.y * ftanh(k0.y + hq0.y + pm * m00.y + p0 * m10.y + pp * m20.y);
        s += Wa0.z * ftanh(k0.z + hq0.z + pm * m00.z + p0 * m10.z + pp * m20.z);
        s += Wa0.w * ftanh(k0.w + hq0.w + pm * m00.w + p0 * m10.w + pp * m20.w);
        s += Wa1.x * ftanh(k1.x + hq1.x + pm * m01.x + p0 * m11.x + pp * m21.x);
        s += Wa1.y * ftanh(k1.y + hq1.y + pm * m01.y + p0 * m11.y + pp * m21.y);
        s += Wa1.z * ftanh(k1.z + hq1.z + pm * m01.z + p0 * m11.z + pp * m21.z);
        s += Wa1.w * ftanh(k1.w + hq1.w + pm * m01.w + p0 * m11.w + pp * m21.w);

#pragma unroll
        for (int off = 16; off; off >>= 1)
            s += __shfl_xor_sync(0xffffffffu, s, off);

        float h = (s + ba >= 0.f) ? ctx_mask[l * BATCH + b] : 0.f;
        if (lane == 0) g_hardU[l * BATCH + b] = h;
        hsum += h;

        if (h != 0.f) {  // warp-uniform: skip ctx_val row entirely when h==0
            float4 v0 = *reinterpret_cast<const float4*>(ctx_val + row + d0);
            float4 v1 = *reinterpret_cast<const float4*>(ctx_val + row + d1);
            acc0.x += h * v0.x; acc0.y += h * v0.y;
            acc0.z += h * v0.z; acc0.w += h * v0.w;
            acc1.x += h * v1.x; acc1.y += h * v1.y;
            acc1.z += h * v1.z; acc1.w += h * v1.w;
        }
    }

    *reinterpret_cast<float4*>(&s_acc[w * DDIM + d0]) = acc0;
    *reinterpret_cast<float4*>(&s_acc[w * DDIM + d1]) = acc1;
    if (lane == 0) s_cnt[w] = hsum;
    __syncthreads();

    int d = threadIdx.x;
    float p = 0.f;
#pragma unroll
    for (int ww = 0; ww < 8; ww++) p += s_acc[ww * DDIM + d];
    g_part[((size_t)b * NCHUNK + chunk) * DDIM + d] = p;

    if (threadIdx.x == 0) {
        float c = 0.f;
#pragma unroll
        for (int ww = 0; ww < 8; ww++) c += s_cnt[ww];
        g_denp[b * NCHUNK + chunk] = c;
    }
}

// ---------------------------------------------------------------------------
// Kernel 3: finish. Normalize; out = concat(ct.flat, hard.flat)
// ---------------------------------------------------------------------------
__global__ __launch_bounds__(256) void finish_kernel(float* __restrict__ out)
{
    int i = blockIdx.x * blockDim.x + threadIdx.x;
    if (i < BATCH * DDIM) {
        int b = i >> 8;
        int d = i & (DDIM - 1);
        float den = 0.f;
#pragma unroll
        for (int c = 0; c < NCHUNK; c++) den += g_denp[b * NCHUNK + c];
        float ct = 0.f;
#pragma unroll
        for (int c = 0; c < NCHUNK; c++)
            ct += g_part[((size_t)b * NCHUNK + c) * DDIM + d];
        out[i] = ct / (den + 1e-10f);
    } else if (i < BATCH * DDIM + L_MAX * BATCH) {
        int j = i - BATCH * DDIM;
        int b = j & (BATCH - 1);
        float den = 0.f;
#pragma unroll
        for (int c = 0; c < NCHUNK; c++) den += g_denp[b * NCHUNK + c];
        out[i] = g_hardU[j] / (den + 1e-10f);
    }
}

// ---------------------------------------------------------------------------
extern "C" void kernel_launch(void* const* d_in, const int* in_sizes, int n_in,
                              void* d_out, int out_size)
{
    (void)in_sizes; (void)n_in; (void)out_size;
    const float* ctx_val  = (const float*)d_in[0];
    const float* ctx_key  = (const float*)d_in[1];
    const float* ctx_mask = (const float*)d_in[2];
    const float* past     = (const float*)d_in[3];
    const float* ht       = (const float*)d_in[4];
    const float* Wc       = (const float*)d_in[5];
    const float* Wq       = (const float*)d_in[6];
    const float* Wap      = (const float*)d_in[7];
    const float* bap      = (const float*)d_in[8];
    const float* Wattn    = (const float*)d_in[9];
    const float* battn    = (const float*)d_in[10];
    float* out = (float*)d_out;

    prep_kernel<<<HQ_BLOCKS + M_BLOCKS, 256>>>(ht, Wq, Wap, Wc, bap);

    dim3 grid(NCHUNK, BATCH);
    main_kernel<<<grid, 256>>>(ctx_val, ctx_key, ctx_mask, past, Wattn, battn);

    int total = BATCH * DDIM + L_MAX * BATCH;
    finish_kernel<<<(total + 255) / 256, 256>>>(out);
}